// round 15
// baseline (speedup 1.0000x reference)
#include <cuda_runtime.h>
#include <cuda_fp16.h>
#include <math_constants.h>

// Problem dims fixed by setup_inputs(): N=100000, E=1600000, Fin=128, H1=2, Fh=32, Fout=128
#define NN 100000
#define EE 1600000
#define ET (EE + NN)

// ---------------- scratch (static device memory; no allocations allowed) ----------------
__device__ int   g_is64;
__device__ int   g_deg[NN];
__device__ int   g_rowptr[NN + 1];
__device__ int   g_cursor[NN];
__device__ int   g_blksum[128];
__device__ int   g_csr[ET];
__device__ __align__(16) __half g_h1h[NN * 64];   // layer1 pre-agg features (fp16 gather table)
__device__ __align__(8) float g_as1[NN * 2];      // alpha_src layer1 [N,H1]
__device__ __align__(8) float g_ad1[NN * 2];      // alpha_dst layer1
__device__ __align__(16) float  g_h1p[NN * 64];   // relu(layer1 out), fp32 (linear reads in gemm2)
__device__ __align__(16) __half g_h2h[NN * 128];  // layer2 pre-agg features (fp16 gather table)
__device__ float g_as2[NN];
__device__ float g_ad2[NN];

__device__ __forceinline__ float lrelu(float x) { return x > 0.f ? x : 0.2f * x; }

__device__ __forceinline__ float wsum(float v) {
    #pragma unroll
    for (int o = 16; o; o >>= 1) v += __shfl_xor_sync(0xffffffffu, v, o);
    return v;
}

__device__ __forceinline__ unsigned h2_to_u(__half2 h) {
    union { __half2 h; unsigned u; } c; c.h = h; return c.u;
}
__device__ __forceinline__ __half2 u_to_h2(unsigned u) {
    union { __half2 h; unsigned u; } c; c.u = u; return c.h;
}

// ---- packed f32x2 helpers (Blackwell: fma.rn.f32x2 = 2 IEEE fp32 FMAs / instr) ----
// W rows are loaded directly as ulonglong2: the 64-bit lanes ARE the packed (w_j, w_j+1)
// f32x2 operands (same bytes), so no pack instructions are needed for W.
__device__ __forceinline__ unsigned long long dup2(float v) {
    unsigned long long r;
    asm("mov.b64 %0, {%1, %1};" : "=l"(r) : "f"(v));
    return r;
}
__device__ __forceinline__ void fma2(unsigned long long& acc, unsigned long long a, unsigned long long b) {
    asm("fma.rn.f32x2 %0, %1, %2, %0;" : "+l"(acc) : "l"(a), "l"(b));
}
__device__ __forceinline__ float2 unpk2(unsigned long long v) {
    float lo, hi;
    asm("mov.b64 {%0, %1}, %2;" : "=f"(lo), "=f"(hi) : "l"(v));
    return make_float2(lo, hi);
}

// ---------------- CSR build ----------------
// edge_index may arrive as int64 (reference dtype) or narrowed to int32 by the
// harness; probe once (int32 read as int64 -> fused indices >= N).
__global__ void k_init_deg(const void* ei, int N) {
    int i = blockIdx.x * blockDim.x + threadIdx.x;
    if (i < N) g_deg[i] = 1;  // self-loop
    if (i == 0) {
        const long long* p = (const long long*)ei;
        int ok = 1;
        #pragma unroll
        for (int k = 0; k < 16; k++) {
            long long v = p[k];
            if (v < 0 || v >= (long long)N) { ok = 0; break; }
        }
        g_is64 = ok;
    }
}

__global__ void k_count(const void* __restrict__ ei, int E, int N) {
    int i = blockIdx.x * blockDim.x + threadIdx.x;
    int e = i * 4;
    if (e >= E) return;
    int d[4];
    if (g_is64) {
        const long long* p = (const long long*)ei + E;
        longlong4 v = *(const longlong4*)&p[e];
        d[0] = (int)v.x; d[1] = (int)v.y; d[2] = (int)v.z; d[3] = (int)v.w;
    } else {
        const int* p = (const int*)ei + E;
        int4 v = *(const int4*)&p[e];
        d[0] = v.x; d[1] = v.y; d[2] = v.z; d[3] = v.w;
    }
    #pragma unroll
    for (int k = 0; k < 4; k++)
        if (e + k < E && (unsigned)d[k] < (unsigned)N) atomicAdd(&g_deg[d[k]], 1);
}

__global__ void k_scan1(int N) {
    __shared__ int sm[1024];
    int idx = blockIdx.x * 1024 + threadIdx.x;
    int v = (idx < N) ? g_deg[idx] : 0;
    sm[threadIdx.x] = v;
    __syncthreads();
    #pragma unroll
    for (int off = 1; off < 1024; off <<= 1) {
        int t = (threadIdx.x >= off) ? sm[threadIdx.x - off] : 0;
        __syncthreads();
        sm[threadIdx.x] += t;
        __syncthreads();
    }
    if (idx < N) g_rowptr[idx] = sm[threadIdx.x] - v;  // exclusive
    if (threadIdx.x == 1023) g_blksum[blockIdx.x] = sm[1023];
}

// scan3 with inline block-sum prefix: each block reduces blksum[0..b-1] itself (<=98 values)
__global__ void k_scan3(int N, int total) {
    __shared__ int ws[4];
    __shared__ int sh_prefix;
    int b = blockIdx.x;
    int t = threadIdx.x;
    if (t < 128) {
        int lane = t & 31, w = t >> 5;
        int v = (t < b) ? g_blksum[t] : 0;   // b <= 97 < 128
        #pragma unroll
        for (int o = 16; o; o >>= 1) v += __shfl_xor_sync(0xffffffffu, v, o);
        if (lane == 0) ws[w] = v;
    }
    __syncthreads();
    if (t == 0) sh_prefix = ws[0] + ws[1] + ws[2] + ws[3];
    __syncthreads();
    int idx = b * 1024 + t;
    if (idx > N) return;
    if (idx == N) { g_rowptr[N] = total; return; }
    int v = g_rowptr[idx] + sh_prefix;
    g_rowptr[idx] = v;
    g_cursor[idx] = v;
}

__global__ void k_fill(const void* __restrict__ ei, int E, int N) {
    int i = blockIdx.x * blockDim.x + threadIdx.x;
    int E4 = (E + 3) >> 2;
    if (i < E4) {
        int e = i * 4;
        int s[4], d[4];
        if (g_is64) {
            const long long* ps = (const long long*)ei;
            const long long* pd = ps + E;
            longlong4 vs = *(const longlong4*)&ps[e];
            longlong4 vd = *(const longlong4*)&pd[e];
            s[0] = (int)vs.x; s[1] = (int)vs.y; s[2] = (int)vs.z; s[3] = (int)vs.w;
            d[0] = (int)vd.x; d[1] = (int)vd.y; d[2] = (int)vd.z; d[3] = (int)vd.w;
        } else {
            const int* ps = (const int*)ei;
            const int* pd = ps + E;
            int4 vs = *(const int4*)&ps[e];
            int4 vd = *(const int4*)&pd[e];
            s[0] = vs.x; s[1] = vs.y; s[2] = vs.z; s[3] = vs.w;
            d[0] = vd.x; d[1] = vd.y; d[2] = vd.z; d[3] = vd.w;
        }
        #pragma unroll
        for (int k = 0; k < 4; k++) {
            if (e + k >= E) break;
            if ((unsigned)d[k] >= (unsigned)N || (unsigned)s[k] >= (unsigned)N) continue;
            int pos = atomicAdd(&g_cursor[d[k]], 1);
            g_csr[pos] = s[k];
        }
    } else {
        int node = i - E4;
        if (node < N) {
            int pos = atomicAdd(&g_cursor[node], 1);
            g_csr[pos] = node;
        }
    }
}

// ---------------- GEMM1: h1 = x @ W1 [128x64] -> fp16 table, fused alpha epilogue ----------------
// 4x4 register block; f32x2 accumulators; W loaded pre-packed as ulonglong2 (no pack movs).
__global__ void __launch_bounds__(256) k_gemm1(const float* __restrict__ x,
                                               const float* __restrict__ W1,
                                               const float* __restrict__ as,
                                               const float* __restrict__ ad, int N) {
    __shared__ float xs[128 * 68];   // 34.8 KB, transposed x tile
    int t = threadIdx.x;
    int tx = t & 15;                 // cols tx*4 .. tx*4+3
    int ty = t >> 4;                 // rows ty*4 .. ty*4+3
    int head = tx >> 3;
    int base = blockIdx.x * 64;

    float4 as4 = ((const float4*)as)[tx];
    float4 ad4 = ((const float4*)ad)[tx];

    for (int i = t; i < 64 * 128; i += 256) {
        int row = i >> 7, k = i & 127;
        int r = base + row;
        xs[k * 68 + row] = (r < N) ? x[r * 128 + k] : 0.f;
    }
    __syncthreads();

    unsigned long long acc2[4][2] = {};
    #pragma unroll 4
    for (int k = 0; k < 128; k++) {
        ulonglong2 wv = __ldg((const ulonglong2*)&W1[k * 64 + tx * 4]);  // (w0,w1),(w2,w3)
        float4 xv = *(const float4*)&xs[k * 68 + ty * 4];
        unsigned long long x0 = dup2(xv.x), x1 = dup2(xv.y), x2 = dup2(xv.z), x3 = dup2(xv.w);
        fma2(acc2[0][0], x0, wv.x); fma2(acc2[0][1], x0, wv.y);
        fma2(acc2[1][0], x1, wv.x); fma2(acc2[1][1], x1, wv.y);
        fma2(acc2[2][0], x2, wv.x); fma2(acc2[2][1], x2, wv.y);
        fma2(acc2[3][0], x3, wv.x); fma2(acc2[3][1], x3, wv.y);
    }

    #pragma unroll
    for (int r = 0; r < 4; r++) {
        int row = base + ty * 4 + r;
        float2 h01 = unpk2(acc2[r][0]);
        float2 h23 = unpk2(acc2[r][1]);
        if (row < N) {
            uint2 pk;
            pk.x = h2_to_u(__floats2half2_rn(h01.x, h01.y));
            pk.y = h2_to_u(__floats2half2_rn(h23.x, h23.y));
            *(uint2*)&g_h1h[row * 64 + tx * 4] = pk;
        }
        float p = h01.x * as4.x + h01.y * as4.y + h23.x * as4.z + h23.y * as4.w;
        float q = h01.x * ad4.x + h01.y * ad4.y + h23.x * ad4.z + h23.y * ad4.w;
        #pragma unroll
        for (int o = 1; o <= 4; o <<= 1) {
            p += __shfl_xor_sync(0xffffffffu, p, o);
            q += __shfl_xor_sync(0xffffffffu, q, o);
        }
        if ((tx & 7) == 0 && row < N) {
            g_as1[row * 2 + head] = p;
            g_ad1[row * 2 + head] = q;
        }
    }
}

// ---------------- Layer1 aggregation: warp-cooperative two-phase ----------------
__global__ void k_agg1(const float* __restrict__ b1, int N) {
    int node = blockIdx.x * 8 + (threadIdx.x >> 5);
    if (node >= N) return;
    int lane = threadIdx.x & 31;
    int hsel = lane >> 4;
    int start = g_rowptr[node], end = g_rowptr[node + 1];
    float2 adp = *(const float2*)&g_ad1[node * 2];
    float2 acc = make_float2(0.f, 0.f);
    float s0 = 0.f, s1 = 0.f;
    for (int b = start; b < end; b += 32) {
        int i = b + lane;
        int src_l = 0; float ex0_l = 0.f, ex1_l = 0.f;
        if (i < end) {
            src_l = g_csr[i];
            float2 a = *(const float2*)&g_as1[src_l * 2];
            ex0_l = __expf(lrelu(a.x + adp.x));
            ex1_l = __expf(lrelu(a.y + adp.y));
        }
        s0 += ex0_l; s1 += ex1_l;
        int cnt = min(32, end - b);
        #pragma unroll 8
        for (int j = 0; j < cnt; j++) {
            int src  = __shfl_sync(0xffffffffu, src_l, j);
            float e0 = __shfl_sync(0xffffffffu, ex0_l, j);
            float e1 = __shfl_sync(0xffffffffu, ex1_l, j);
            float exh = hsel ? e1 : e0;
            float2 v = __half22float2(*(const __half2*)&g_h1h[src * 64 + lane * 2]);
            acc.x += exh * v.x; acc.y += exh * v.y;
        }
    }
    s0 = wsum(s0); s1 = wsum(s1);
    float inv = 1.f / (hsel ? s1 : s0);
    float2 bb = ((const float2*)b1)[lane];
    float2 o = make_float2(fmaxf(acc.x * inv + bb.x, 0.f), fmaxf(acc.y * inv + bb.y, 0.f));
    *(float2*)&g_h1p[node * 64 + lane * 2] = o;
}

// ---------------- GEMM2: h2 = h1p @ W2 [64x128] -> fp16 table, fused alpha2 ----------------
__global__ void __launch_bounds__(256) k_gemm2(const float* __restrict__ W2,
                                               const float* __restrict__ as,
                                               const float* __restrict__ ad, int N) {
    __shared__ float xs[64 * 68];    // 17.4 KB
    int t = threadIdx.x;
    int tx = t & 15;                 // cols tx*8 .. tx*8+7
    int ty = t >> 4;                 // rows ty*4 .. ty*4+3
    int base = blockIdx.x * 64;

    float4 asA = ((const float4*)as)[tx * 2], asB = ((const float4*)as)[tx * 2 + 1];
    float4 adA = ((const float4*)ad)[tx * 2], adB = ((const float4*)ad)[tx * 2 + 1];

    for (int i = t; i < 64 * 64; i += 256) {
        int row = i >> 6, k = i & 63;
        int r = base + row;
        xs[k * 68 + row] = (r < N) ? g_h1p[r * 64 + k] : 0.f;
    }
    __syncthreads();

    unsigned long long acc2[4][4] = {};
    #pragma unroll 4
    for (int k = 0; k < 64; k++) {
        ulonglong2 wva = __ldg((const ulonglong2*)&W2[k * 128 + tx * 8]);
        ulonglong2 wvb = __ldg((const ulonglong2*)&W2[k * 128 + tx * 8 + 4]);
        float4 xv = *(const float4*)&xs[k * 68 + ty * 4];
        unsigned long long xd[4] = { dup2(xv.x), dup2(xv.y), dup2(xv.z), dup2(xv.w) };
        #pragma unroll
        for (int r = 0; r < 4; r++) {
            fma2(acc2[r][0], xd[r], wva.x);
            fma2(acc2[r][1], xd[r], wva.y);
            fma2(acc2[r][2], xd[r], wvb.x);
            fma2(acc2[r][3], xd[r], wvb.y);
        }
    }

    #pragma unroll
    for (int r = 0; r < 4; r++) {
        int row = base + ty * 4 + r;
        float2 h0 = unpk2(acc2[r][0]), h1 = unpk2(acc2[r][1]);
        float2 h2 = unpk2(acc2[r][2]), h3 = unpk2(acc2[r][3]);
        if (row < N) {
            uint4 pk;
            pk.x = h2_to_u(__floats2half2_rn(h0.x, h0.y));
            pk.y = h2_to_u(__floats2half2_rn(h1.x, h1.y));
            pk.z = h2_to_u(__floats2half2_rn(h2.x, h2.y));
            pk.w = h2_to_u(__floats2half2_rn(h3.x, h3.y));
            *(uint4*)&g_h2h[row * 128 + tx * 8] = pk;
        }
        float p = h0.x * asA.x + h0.y * asA.y + h1.x * asA.z + h1.y * asA.w
                + h2.x * asB.x + h2.y * asB.y + h3.x * asB.z + h3.y * asB.w;
        float q = h0.x * adA.x + h0.y * adA.y + h1.x * adA.z + h1.y * adA.w
                + h2.x * adB.x + h2.y * adB.y + h3.x * adB.z + h3.y * adB.w;
        #pragma unroll
        for (int o = 1; o <= 8; o <<= 1) {
            p += __shfl_xor_sync(0xffffffffu, p, o);
            q += __shfl_xor_sync(0xffffffffu, q, o);
        }
        if (tx == 0 && row < N) { g_as2[row] = p; g_ad2[row] = q; }
    }
}

// ---------------- Layer2 aggregation: warp-cooperative two-phase, fp16 gather ----------------
__global__ void k_agg2(const float* __restrict__ b2, int N, float* __restrict__ out) {
    int node = blockIdx.x * 8 + (threadIdx.x >> 5);
    if (node >= N) return;
    int lane = threadIdx.x & 31;
    int start = g_rowptr[node], end = g_rowptr[node + 1];
    float ad = g_ad2[node];
    float4 acc = make_float4(0.f, 0.f, 0.f, 0.f);
    float spart = 0.f;
    for (int b = start; b < end; b += 32) {
        int i = b + lane;
        int src_l = 0; float ex_l = 0.f;
        if (i < end) {
            src_l = g_csr[i];
            ex_l = __expf(lrelu(g_as2[src_l] + ad));
        }
        spart += ex_l;
        int cnt = min(32, end - b);
        #pragma unroll 8
        for (int j = 0; j < cnt; j++) {
            int src  = __shfl_sync(0xffffffffu, src_l, j);
            float ex = __shfl_sync(0xffffffffu, ex_l, j);
            uint2 pk = *(const uint2*)&g_h2h[src * 128 + lane * 4];
            float2 v0 = __half22float2(u_to_h2(pk.x));
            float2 v1 = __half22float2(u_to_h2(pk.y));
            acc.x += ex * v0.x; acc.y += ex * v0.y;
            acc.z += ex * v1.x; acc.w += ex * v1.y;
        }
    }
    float inv = 1.f / wsum(spart);
    float4 bb = ((const float4*)b2)[lane];
    float4 o;
    o.x = acc.x * inv + bb.x;
    o.y = acc.y * inv + bb.y;
    o.z = acc.z * inv + bb.z;
    o.w = acc.w * inv + bb.w;
    ((float4*)out)[node * 32 + lane] = o;
}

// ---------------- launch: serial (deterministic order -> ncu -s 5 captures k_gemm1) ----------------
extern "C" void kernel_launch(void* const* d_in, const int* in_sizes, int n_in,
                              void* d_out, int out_size) {
    const float* x   = (const float*)d_in[0];
    const void*  ei  = d_in[1];
    const float* W1  = (const float*)d_in[2];
    const float* as1 = (const float*)d_in[3];
    const float* ad1 = (const float*)d_in[4];
    const float* b1  = (const float*)d_in[5];
    const float* W2  = (const float*)d_in[6];
    const float* as2 = (const float*)d_in[7];
    const float* ad2 = (const float*)d_in[8];
    const float* b2  = (const float*)d_in[9];
    float* out = (float*)d_out;

    int N = in_sizes[0] / 128;
    int E = in_sizes[1] / 2;

    k_init_deg<<<(N + 255) / 256, 256>>>(ei, N);
    k_count<<<(E / 4 + 255) / 256, 256>>>(ei, E, N);
    int nb = (N + 1023) / 1024;
    k_scan1<<<nb, 1024>>>(N);
    k_scan3<<<nb, 1024>>>(N, E + N);
    {
        int E4 = (E + 3) / 4;
        k_fill<<<(E4 + N + 255) / 256, 256>>>(ei, E, N);
    }
    int ng = (N + 63) / 64;
    k_gemm1<<<ng, 256>>>(x, W1, as1, ad1, N);
    k_agg1<<<(N + 7) / 8, 256>>>(b1, N);
    k_gemm2<<<ng, 256>>>(W2, as2, ad2, N);
    k_agg2<<<(N + 7) / 8, 256>>>(b2, N, out);
}

// round 17
// speedup vs baseline: 1.0312x; 1.0312x over previous
#include <cuda_runtime.h>
#include <cuda_fp16.h>
#include <math_constants.h>

// Problem dims fixed by setup_inputs(): N=100000, E=1600000, Fin=128, H1=2, Fh=32, Fout=128
#define NN 100000
#define EE 1600000
#define ET (EE + NN)

// ---------------- scratch (static device memory; no allocations allowed) ----------------
__device__ int   g_is64;
__device__ int   g_deg[NN];          // zero at module load; scan1 re-zeroes each replay
__device__ int   g_rowptr[NN + 1];
__device__ int   g_cursor[NN];
__device__ int   g_blksum[128];
__device__ int   g_csr[ET];
__device__ __align__(16) __half g_h1h[NN * 64];   // layer1 pre-agg features (fp16 gather table)
__device__ __align__(8) float g_as1[NN * 2];      // alpha_src layer1 [N,H1]
__device__ __align__(8) float g_ad1[NN * 2];      // alpha_dst layer1
__device__ __align__(16) float  g_h1p[NN * 64];   // relu(layer1 out), fp32 (linear reads in gemm2)
__device__ __align__(16) __half g_h2h[NN * 128];  // layer2 pre-agg features (fp16 gather table)
__device__ float g_as2[NN];
__device__ float g_ad2[NN];

__device__ __forceinline__ float lrelu(float x) { return x > 0.f ? x : 0.2f * x; }

__device__ __forceinline__ float wsum(float v) {
    #pragma unroll
    for (int o = 16; o; o >>= 1) v += __shfl_xor_sync(0xffffffffu, v, o);
    return v;
}

__device__ __forceinline__ unsigned h2_to_u(__half2 h) {
    union { __half2 h; unsigned u; } c; c.h = h; return c.u;
}
__device__ __forceinline__ __half2 u_to_h2(unsigned u) {
    union { __half2 h; unsigned u; } c; c.u = u; return c.h;
}

// ---- packed f32x2 helpers (Blackwell: fma.rn.f32x2 = 2 IEEE fp32 FMAs / instr) ----
// W rows are loaded directly as ulonglong2: the 64-bit lanes ARE the packed (w_j, w_j+1)
// f32x2 operands (same bytes), so no pack instructions are needed for W.
__device__ __forceinline__ unsigned long long dup2(float v) {
    unsigned long long r;
    asm("mov.b64 %0, {%1, %1};" : "=l"(r) : "f"(v));
    return r;
}
__device__ __forceinline__ void fma2(unsigned long long& acc, unsigned long long a, unsigned long long b) {
    asm("fma.rn.f32x2 %0, %1, %2, %0;" : "+l"(acc) : "l"(a), "l"(b));
}
__device__ __forceinline__ float2 unpk2(unsigned long long v) {
    float lo, hi;
    asm("mov.b64 {%0, %1}, %2;" : "=f"(lo), "=f"(hi) : "l"(v));
    return make_float2(lo, hi);
}

// ---------------- CSR build ----------------
// edge_index may arrive as int64 (reference dtype) or narrowed to int32 by the
// harness; probe once (int32 read as int64 -> fused indices >= N).
__global__ void k_probe(const void* ei, int N) {
    if (threadIdx.x == 0) {
        const long long* p = (const long long*)ei;
        int ok = 1;
        #pragma unroll
        for (int k = 0; k < 16; k++) {
            long long v = p[k];
            if (v < 0 || v >= (long long)N) { ok = 0; break; }
        }
        g_is64 = ok;
    }
}

__global__ void k_count(const void* __restrict__ ei, int E, int N) {
    int i = blockIdx.x * blockDim.x + threadIdx.x;
    int e = i * 4;
    if (e >= E) return;
    int d[4];
    if (g_is64) {
        const long long* p = (const long long*)ei + E;
        longlong4 v = *(const longlong4*)&p[e];
        d[0] = (int)v.x; d[1] = (int)v.y; d[2] = (int)v.z; d[3] = (int)v.w;
    } else {
        const int* p = (const int*)ei + E;
        int4 v = *(const int4*)&p[e];
        d[0] = v.x; d[1] = v.y; d[2] = v.z; d[3] = v.w;
    }
    #pragma unroll
    for (int k = 0; k < 4; k++)
        if (e + k < E && (unsigned)d[k] < (unsigned)N) atomicAdd(&g_deg[d[k]], 1);
}

// scan1: deg+1 (inline self-loop), exclusive block scan, and RESET deg to 0 for the next replay.
__global__ void k_scan1(int N) {
    __shared__ int sm[1024];
    int idx = blockIdx.x * 1024 + threadIdx.x;
    int v = 0;
    if (idx < N) {
        v = g_deg[idx] + 1;     // +1 = self-loop
        g_deg[idx] = 0;         // reset for next graph replay
    }
    sm[threadIdx.x] = v;
    __syncthreads();
    #pragma unroll
    for (int off = 1; off < 1024; off <<= 1) {
        int t = (threadIdx.x >= off) ? sm[threadIdx.x - off] : 0;
        __syncthreads();
        sm[threadIdx.x] += t;
        __syncthreads();
    }
    if (idx < N) g_rowptr[idx] = sm[threadIdx.x] - v;  // exclusive
    if (threadIdx.x == 1023) g_blksum[blockIdx.x] = sm[1023];
}

// scan3 with inline block-sum prefix: each block reduces blksum[0..b-1] itself (<=98 values)
__global__ void k_scan3(int N, int total) {
    __shared__ int ws[4];
    __shared__ int sh_prefix;
    int b = blockIdx.x;
    int t = threadIdx.x;
    if (t < 128) {
        int lane = t & 31, w = t >> 5;
        int v = (t < b) ? g_blksum[t] : 0;   // b <= 97 < 128
        #pragma unroll
        for (int o = 16; o; o >>= 1) v += __shfl_xor_sync(0xffffffffu, v, o);
        if (lane == 0) ws[w] = v;
    }
    __syncthreads();
    if (t == 0) sh_prefix = ws[0] + ws[1] + ws[2] + ws[3];
    __syncthreads();
    int idx = b * 1024 + t;
    if (idx > N) return;
    if (idx == N) { g_rowptr[N] = total; return; }
    int v = g_rowptr[idx] + sh_prefix;
    g_rowptr[idx] = v;
    g_cursor[idx] = v;
}

__global__ void k_fill(const void* __restrict__ ei, int E, int N) {
    int i = blockIdx.x * blockDim.x + threadIdx.x;
    int E4 = (E + 3) >> 2;
    if (i < E4) {
        int e = i * 4;
        int s[4], d[4];
        if (g_is64) {
            const long long* ps = (const long long*)ei;
            const long long* pd = ps + E;
            longlong4 vs = *(const longlong4*)&ps[e];
            longlong4 vd = *(const longlong4*)&pd[e];
            s[0] = (int)vs.x; s[1] = (int)vs.y; s[2] = (int)vs.z; s[3] = (int)vs.w;
            d[0] = (int)vd.x; d[1] = (int)vd.y; d[2] = (int)vd.z; d[3] = (int)vd.w;
        } else {
            const int* ps = (const int*)ei;
            const int* pd = ps + E;
            int4 vs = *(const int4*)&ps[e];
            int4 vd = *(const int4*)&pd[e];
            s[0] = vs.x; s[1] = vs.y; s[2] = vs.z; s[3] = vs.w;
            d[0] = vd.x; d[1] = vd.y; d[2] = vd.z; d[3] = vd.w;
        }
        #pragma unroll
        for (int k = 0; k < 4; k++) {
            if (e + k >= E) break;
            if ((unsigned)d[k] >= (unsigned)N || (unsigned)s[k] >= (unsigned)N) continue;
            int pos = atomicAdd(&g_cursor[d[k]], 1);
            g_csr[pos] = s[k];
        }
    } else {
        int node = i - E4;
        if (node < N) {
            int pos = atomicAdd(&g_cursor[node], 1);
            g_csr[pos] = node;
        }
    }
}

// ---------------- GEMM1: h1 = x @ W1 [128x64] -> fp16 table, fused alpha epilogue ----------------
// 4x4 register block; f32x2 accumulators; W loaded pre-packed as ulonglong2 (no pack movs).
__global__ void __launch_bounds__(256) k_gemm1(const float* __restrict__ x,
                                               const float* __restrict__ W1,
                                               const float* __restrict__ as,
                                               const float* __restrict__ ad, int N) {
    __shared__ float xs[128 * 68];   // 34.8 KB, transposed x tile
    int t = threadIdx.x;
    int tx = t & 15;                 // cols tx*4 .. tx*4+3
    int ty = t >> 4;                 // rows ty*4 .. ty*4+3
    int head = tx >> 3;
    int base = blockIdx.x * 64;

    float4 as4 = ((const float4*)as)[tx];
    float4 ad4 = ((const float4*)ad)[tx];

    for (int i = t; i < 64 * 128; i += 256) {
        int row = i >> 7, k = i & 127;
        int r = base + row;
        xs[k * 68 + row] = (r < N) ? x[r * 128 + k] : 0.f;
    }
    __syncthreads();

    unsigned long long acc2[4][2] = {};
    #pragma unroll 4
    for (int k = 0; k < 128; k++) {
        ulonglong2 wv = __ldg((const ulonglong2*)&W1[k * 64 + tx * 4]);  // (w0,w1),(w2,w3)
        float4 xv = *(const float4*)&xs[k * 68 + ty * 4];
        unsigned long long x0 = dup2(xv.x), x1 = dup2(xv.y), x2 = dup2(xv.z), x3 = dup2(xv.w);
        fma2(acc2[0][0], x0, wv.x); fma2(acc2[0][1], x0, wv.y);
        fma2(acc2[1][0], x1, wv.x); fma2(acc2[1][1], x1, wv.y);
        fma2(acc2[2][0], x2, wv.x); fma2(acc2[2][1], x2, wv.y);
        fma2(acc2[3][0], x3, wv.x); fma2(acc2[3][1], x3, wv.y);
    }

    #pragma unroll
    for (int r = 0; r < 4; r++) {
        int row = base + ty * 4 + r;
        float2 h01 = unpk2(acc2[r][0]);
        float2 h23 = unpk2(acc2[r][1]);
        if (row < N) {
            uint2 pk;
            pk.x = h2_to_u(__floats2half2_rn(h01.x, h01.y));
            pk.y = h2_to_u(__floats2half2_rn(h23.x, h23.y));
            *(uint2*)&g_h1h[row * 64 + tx * 4] = pk;
        }
        float p = h01.x * as4.x + h01.y * as4.y + h23.x * as4.z + h23.y * as4.w;
        float q = h01.x * ad4.x + h01.y * ad4.y + h23.x * ad4.z + h23.y * ad4.w;
        #pragma unroll
        for (int o = 1; o <= 4; o <<= 1) {
            p += __shfl_xor_sync(0xffffffffu, p, o);
            q += __shfl_xor_sync(0xffffffffu, q, o);
        }
        if ((tx & 7) == 0 && row < N) {
            g_as1[row * 2 + head] = p;
            g_ad1[row * 2 + head] = q;
        }
    }
}

// ---------------- Layer1 aggregation: warp-cooperative two-phase ----------------
__global__ void k_agg1(const float* __restrict__ b1, int N) {
    int node = blockIdx.x * 8 + (threadIdx.x >> 5);
    if (node >= N) return;
    int lane = threadIdx.x & 31;
    int hsel = lane >> 4;
    int start = g_rowptr[node], end = g_rowptr[node + 1];
    float2 adp = *(const float2*)&g_ad1[node * 2];
    float2 acc = make_float2(0.f, 0.f);
    float s0 = 0.f, s1 = 0.f;
    for (int b = start; b < end; b += 32) {
        int i = b + lane;
        int src_l = 0; float ex0_l = 0.f, ex1_l = 0.f;
        if (i < end) {
            src_l = g_csr[i];
            float2 a = *(const float2*)&g_as1[src_l * 2];
            ex0_l = __expf(lrelu(a.x + adp.x));
            ex1_l = __expf(lrelu(a.y + adp.y));
        }
        s0 += ex0_l; s1 += ex1_l;
        int cnt = min(32, end - b);
        #pragma unroll 8
        for (int j = 0; j < cnt; j++) {
            int src  = __shfl_sync(0xffffffffu, src_l, j);
            float e0 = __shfl_sync(0xffffffffu, ex0_l, j);
            float e1 = __shfl_sync(0xffffffffu, ex1_l, j);
            float exh = hsel ? e1 : e0;
            float2 v = __half22float2(*(const __half2*)&g_h1h[src * 64 + lane * 2]);
            acc.x += exh * v.x; acc.y += exh * v.y;
        }
    }
    s0 = wsum(s0); s1 = wsum(s1);
    float inv = 1.f / (hsel ? s1 : s0);
    float2 bb = ((const float2*)b1)[lane];
    float2 o = make_float2(fmaxf(acc.x * inv + bb.x, 0.f), fmaxf(acc.y * inv + bb.y, 0.f));
    *(float2*)&g_h1p[node * 64 + lane * 2] = o;
}

// ---------------- GEMM2: h2 = h1p @ W2 [64x128] -> fp16 table, fused alpha2 ----------------
__global__ void __launch_bounds__(256) k_gemm2(const float* __restrict__ W2,
                                               const float* __restrict__ as,
                                               const float* __restrict__ ad, int N) {
    __shared__ float xs[64 * 68];    // 17.4 KB
    int t = threadIdx.x;
    int tx = t & 15;                 // cols tx*8 .. tx*8+7
    int ty = t >> 4;                 // rows ty*4 .. ty*4+3
    int base = blockIdx.x * 64;

    float4 asA = ((const float4*)as)[tx * 2], asB = ((const float4*)as)[tx * 2 + 1];
    float4 adA = ((const float4*)ad)[tx * 2], adB = ((const float4*)ad)[tx * 2 + 1];

    for (int i = t; i < 64 * 64; i += 256) {
        int row = i >> 6, k = i & 63;
        int r = base + row;
        xs[k * 68 + row] = (r < N) ? g_h1p[r * 64 + k] : 0.f;
    }
    __syncthreads();

    unsigned long long acc2[4][4] = {};
    #pragma unroll 4
    for (int k = 0; k < 64; k++) {
        ulonglong2 wva = __ldg((const ulonglong2*)&W2[k * 128 + tx * 8]);
        ulonglong2 wvb = __ldg((const ulonglong2*)&W2[k * 128 + tx * 8 + 4]);
        float4 xv = *(const float4*)&xs[k * 68 + ty * 4];
        unsigned long long xd[4] = { dup2(xv.x), dup2(xv.y), dup2(xv.z), dup2(xv.w) };
        #pragma unroll
        for (int r = 0; r < 4; r++) {
            fma2(acc2[r][0], xd[r], wva.x);
            fma2(acc2[r][1], xd[r], wva.y);
            fma2(acc2[r][2], xd[r], wvb.x);
            fma2(acc2[r][3], xd[r], wvb.y);
        }
    }

    #pragma unroll
    for (int r = 0; r < 4; r++) {
        int row = base + ty * 4 + r;
        float2 h0 = unpk2(acc2[r][0]), h1 = unpk2(acc2[r][1]);
        float2 h2 = unpk2(acc2[r][2]), h3 = unpk2(acc2[r][3]);
        if (row < N) {
            uint4 pk;
            pk.x = h2_to_u(__floats2half2_rn(h0.x, h0.y));
            pk.y = h2_to_u(__floats2half2_rn(h1.x, h1.y));
            pk.z = h2_to_u(__floats2half2_rn(h2.x, h2.y));
            pk.w = h2_to_u(__floats2half2_rn(h3.x, h3.y));
            *(uint4*)&g_h2h[row * 128 + tx * 8] = pk;
        }
        float p = h0.x * asA.x + h0.y * asA.y + h1.x * asA.z + h1.y * asA.w
                + h2.x * asB.x + h2.y * asB.y + h3.x * asB.z + h3.y * asB.w;
        float q = h0.x * adA.x + h0.y * adA.y + h1.x * adA.z + h1.y * adA.w
                + h2.x * adB.x + h2.y * adB.y + h3.x * adB.z + h3.y * adB.w;
        #pragma unroll
        for (int o = 1; o <= 8; o <<= 1) {
            p += __shfl_xor_sync(0xffffffffu, p, o);
            q += __shfl_xor_sync(0xffffffffu, q, o);
        }
        if (tx == 0 && row < N) { g_as2[row] = p; g_ad2[row] = q; }
    }
}

// ---------------- Layer2 aggregation: warp-cooperative two-phase, fp16 gather ----------------
__global__ void k_agg2(const float* __restrict__ b2, int N, float* __restrict__ out) {
    int node = blockIdx.x * 8 + (threadIdx.x >> 5);
    if (node >= N) return;
    int lane = threadIdx.x & 31;
    int start = g_rowptr[node], end = g_rowptr[node + 1];
    float ad = g_ad2[node];
    float4 acc = make_float4(0.f, 0.f, 0.f, 0.f);
    float spart = 0.f;
    for (int b = start; b < end; b += 32) {
        int i = b + lane;
        int src_l = 0; float ex_l = 0.f;
        if (i < end) {
            src_l = g_csr[i];
            ex_l = __expf(lrelu(g_as2[src_l] + ad));
        }
        spart += ex_l;
        int cnt = min(32, end - b);
        #pragma unroll 8
        for (int j = 0; j < cnt; j++) {
            int src  = __shfl_sync(0xffffffffu, src_l, j);
            float ex = __shfl_sync(0xffffffffu, ex_l, j);
            uint2 pk = *(const uint2*)&g_h2h[src * 128 + lane * 4];
            float2 v0 = __half22float2(u_to_h2(pk.x));
            float2 v1 = __half22float2(u_to_h2(pk.y));
            acc.x += ex * v0.x; acc.y += ex * v0.y;
            acc.z += ex * v1.x; acc.w += ex * v1.y;
        }
    }
    float inv = 1.f / wsum(spart);
    float4 bb = ((const float4*)b2)[lane];
    float4 o;
    o.x = acc.x * inv + bb.x;
    o.y = acc.y * inv + bb.y;
    o.z = acc.z * inv + bb.z;
    o.w = acc.w * inv + bb.w;
    ((float4*)out)[node * 32 + lane] = o;
}

// ---------------- launch: fork CSR build onto a side stream, overlap with GEMM1 ----------------
extern "C" void kernel_launch(void* const* d_in, const int* in_sizes, int n_in,
                              void* d_out, int out_size) {
    const float* x   = (const float*)d_in[0];
    const void*  ei  = d_in[1];
    const float* W1  = (const float*)d_in[2];
    const float* as1 = (const float*)d_in[3];
    const float* ad1 = (const float*)d_in[4];
    const float* b1  = (const float*)d_in[5];
    const float* W2  = (const float*)d_in[6];
    const float* as2 = (const float*)d_in[7];
    const float* ad2 = (const float*)d_in[8];
    const float* b2  = (const float*)d_in[9];
    float* out = (float*)d_out;

    int N = in_sizes[0] / 128;
    int E = in_sizes[1] / 2;

    static cudaStream_t s2 = nullptr;
    static cudaEvent_t evFork = nullptr, evJoin = nullptr;
    if (!s2) {
        cudaStreamCreateWithFlags(&s2, cudaStreamNonBlocking);
        cudaEventCreateWithFlags(&evFork, cudaEventDisableTiming);
        cudaEventCreateWithFlags(&evJoin, cudaEventDisableTiming);
    }

    // fork: CSR build on s2
    cudaEventRecord(evFork, 0);
    cudaStreamWaitEvent(s2, evFork, 0);
    k_probe<<<1, 32, 0, s2>>>(ei, N);
    k_count<<<(E / 4 + 255) / 256, 256, 0, s2>>>(ei, E, N);
    int nb = (N + 1023) / 1024;
    k_scan1<<<nb, 1024, 0, s2>>>(N);
    k_scan3<<<nb, 1024, 0, s2>>>(N, E + N);
    {
        int E4 = (E + 3) / 4;
        k_fill<<<(E4 + N + 255) / 256, 256, 0, s2>>>(ei, E, N);
    }
    cudaEventRecord(evJoin, s2);

    // concurrent: GEMM1 on the main (capture) stream
    int ng = (N + 63) / 64;
    k_gemm1<<<ng, 256>>>(x, W1, as1, ad1, N);

    // join, then the dependent tail
    cudaStreamWaitEvent(0, evJoin, 0);
    k_agg1<<<(N + 7) / 8, 256>>>(b1, N);
    k_gemm2<<<ng, 256>>>(W2, as2, ad2, N);
    k_agg2<<<(N + 7) / 8, 256>>>(b2, N, out);
}